// round 10
// baseline (speedup 1.0000x reference)
#include <cuda_runtime.h>
#include <cuda_fp16.h>
#include <math.h>

#define NFEAT 18
#define NTRK  1500
#define BSZ   64
#define NTRACK (BSZ*NTRK)        // 96000
#define HID   256
#define TSTEPS 6
#define NT_TILE 32               // tracks per CTA (2 staggered groups of 16)
#define CTA_THREADS 256

// output layout offsets (floats)
#define OUT_POS   24576000       // 96000*256
#define OUT_LOGPT 36864000       // + 96000*128
#define OUT_ETA   36960000
#define OUT_PHI   37056000

typedef unsigned long long u64;
typedef unsigned int u32;

// ---------------- device scratch: fragment-packed fp16 weights ----------------
// LSTM mats: ((((w*4 + g)*8 + kc)*32 + lane)*4 + reg)*2 + dd
__device__ __align__(16) __half P_hh0[65536];
__device__ __align__(16) __half P_ih1[65536];
__device__ __align__(16) __half P_hh1[65536];
__device__ __align__(16) __half P_w0 [32768];   // [8w][2mt][8kc][32][4][2]
__device__ __align__(16) __half P_w1 [65536];   // [8w][2kh][2mt][8kc][32][4][2]
__device__ __align__(16) float g_b0c[512];      // b_ih0+b_hh0, row = g*128+unit
__device__ __align__(16) float g_b1c[512];
__device__ float g_posmul[64];

// ---------------- prep: pack weights into mma fragment order ----------------
__global__ void prep_kernel(const float* __restrict__ W_hh0,
                            const float* __restrict__ b_ih0, const float* __restrict__ b_hh0,
                            const float* __restrict__ W_ih1, const float* __restrict__ W_hh1,
                            const float* __restrict__ b_ih1, const float* __restrict__ b_hh1,
                            const float* __restrict__ mw0,   const float* __restrict__ mw1)
{
    int stride = gridDim.x * blockDim.x;
    int idx0 = blockIdx.x * blockDim.x + threadIdx.x;

    // LSTM hh0 / ih1 / hh1: M-tile = gate (4 per warp), K=128 (8 kc)
    for (int i = idx0; i < 65536; i += stride) {
        int dd = i & 1, reg = (i >> 1) & 3, lane = (i >> 3) & 31;
        int kc = (i >> 8) & 7, g = (i >> 11) & 3, w = (i >> 13) & 7;
        int row = g * 128 + w * 16 + (lane >> 2) + 8 * (reg & 1);
        int col = kc * 16 + (lane & 3) * 2 + dd + 8 * (reg >> 1);
        P_hh0[i] = __float2half_rn(W_hh0[row * 128 + col]);
        P_ih1[i] = __float2half_rn(W_ih1[row * 128 + col]);
        P_hh1[i] = __float2half_rn(W_hh1[row * 128 + col]);
    }
    // MLP0, K=128 part (cols 3..130 of mw0)
    for (int i = idx0; i < 32768; i += stride) {
        int dd = i & 1, reg = (i >> 1) & 3, lane = (i >> 3) & 31;
        int kc = (i >> 8) & 7, mt = (i >> 11) & 1, w = (i >> 12) & 7;
        int row = w * 32 + mt * 16 + (lane >> 2) + 8 * (reg & 1);
        int k   = kc * 16 + (lane & 3) * 2 + dd + 8 * (reg >> 1);
        P_w0[i] = __float2half_rn(mw0[row * 131 + 3 + k]);
    }
    // MLP1, K=256, kh-major: [8w][2kh][2mt][8kc]  (matches the two NKC=8 gemm calls)
    for (int i = idx0; i < 65536; i += stride) {
        int dd = i & 1, reg = (i >> 1) & 3, lane = (i >> 3) & 31;
        int kc = (i >> 8) & 7, mt = (i >> 11) & 1, kh = (i >> 12) & 1, w = (i >> 13) & 7;
        int row = w * 32 + mt * 16 + (lane >> 2) + 8 * (reg & 1);
        int k   = (kh * 8 + kc) * 16 + (lane & 3) * 2 + dd + 8 * (reg >> 1);
        P_w1[i] = __float2half_rn(mw1[row * 256 + k]);
    }
    for (int i = idx0; i < 512; i += stride) {
        g_b0c[i] = b_ih0[i] + b_hh0[i];
        g_b1c[i] = b_ih1[i] + b_hh1[i];
    }
    for (int i = idx0; i < 64; i += stride) {
        float e = (float)(2 * (i >> 1)) * (1.0f / 64.0f);
        g_posmul[i] = 6.283185307179586f / powf(10000.0f, e);
    }
}

// ---------------- activations (MUFU.TANH based) ----------------
__device__ __forceinline__ float tanh_mufu(float x) {
    float r; asm("tanh.approx.f32 %0, %1;" : "=f"(r) : "f"(x)); return r;
}
__device__ __forceinline__ float sigf(float x) {
    return fmaf(tanh_mufu(0.5f * x), 0.5f, 0.5f);
}

// ---------------- mma.sync wrapper ----------------
__device__ __forceinline__ void mma16816(float c[4], u32 a0, u32 a1, u32 a2, u32 a3,
                                         u32 b0, u32 b1) {
    asm("mma.sync.aligned.m16n8k16.row.col.f32.f16.f16.f32 "
        "{%0,%1,%2,%3}, {%4,%5,%6,%7}, {%8,%9}, {%0,%1,%2,%3};"
        : "+f"(c[0]), "+f"(c[1]), "+f"(c[2]), "+f"(c[3])
        : "r"(a0), "r"(a1), "r"(a2), "r"(a3), "r"(b0), "r"(b1));
}

// hB layout (half index): entry(kc, c, col) = 4 halves [kp0dd0, kp0dd1, kp1dd0, kp1dd1]
//   half_idx = ((kc*4 + c)*32 + col)*4 + kp*2 + dd,  unit u = kc*16 + 2c + dd + 8kp
__device__ __forceinline__ int hb_widx(int u, int n) {
    return ((u >> 4) * 4 + ((u & 7) >> 1)) * 128 + n * 4 + ((u >> 3) & 1) * 2 + (u & 1);
}

// fragment GEMM: acc[MT][NTT][4] += Wpacked * B(hB cols gofs..gofs+8*NTT-1)
template<int MT, int NKC, int NTT>
__device__ __forceinline__ void gemm_frag(float acc[][NTT][4],
                                          const __half* __restrict__ pw,
                                          const __half* __restrict__ hB, int lane, int gofs)
{
    const int c = lane & 3, colr = lane >> 2;
#pragma unroll
    for (int kc = 0; kc < NKC; ++kc) {
        u64 bv[NTT];
#pragma unroll
        for (int nt = 0; nt < NTT; ++nt)
            bv[nt] = *reinterpret_cast<const u64*>(hB + ((kc * 4 + c) * 32 + gofs + nt * 8 + colr) * 4);
#pragma unroll
        for (int mt = 0; mt < MT; ++mt) {
            uint4 a = *reinterpret_cast<const uint4*>(pw + ((mt * NKC + kc) * 32 + lane) * 8);
#pragma unroll
            for (int nt = 0; nt < NTT; ++nt)
                mma16816(acc[mt][nt], a.x, a.y, a.z, a.w,
                         (u32)bv[nt], (u32)(bv[nt] >> 32));
        }
    }
}

// ---------------- LSTM epilogue for one 16-track group ----------------
__device__ __forceinline__ void epi_lstm(float acc[4][2][4], float* cst, __half* hbuf,
                                         int g16, int w16, int lr, int c2)
{
#pragma unroll
    for (int nt = 0; nt < 2; ++nt)
#pragma unroll
        for (int idx = 0; idx < 4; ++idx) {
            float iv = sigf(acc[0][nt][idx]);
            float fv = sigf(acc[1][nt][idx]);
            float gv = tanh_mufu(acc[2][nt][idx]);
            float ov = sigf(acc[3][nt][idx]);
            float& cc = cst[nt * 4 + idx];
            cc = fv * cc + iv * gv;
            float h = ov * tanh_mufu(cc);
            int u = w16 + lr + 8 * (idx >> 1);
            int n = g16 + nt * 8 + c2 + (idx & 1);
            hbuf[hb_widx(u, n)] = __float2half_rn(h);
        }
}

// ---------------- fused LSTM + MLP (tensor-core, staggered 16-track groups) ----------------
__global__ void __launch_bounds__(CTA_THREADS, 2)
lstm_mlp_kernel(const float* __restrict__ tf,
                const float* __restrict__ W_ih0,   // [512][2] row-major
                const float* __restrict__ mw0,     // [256][131]
                const float* __restrict__ mb0,
                const float* __restrict__ mb1,
                float* __restrict__ out)
{
    const int tid  = threadIdx.x;
    const int lane = tid & 31;
    const int w    = tid >> 5;
    const int track0 = blockIdx.x * NT_TILE;
    const int lr = lane >> 2, c2 = (lane & 3) * 2;
    const int w16 = w * 16;

    __shared__ __align__(16) __half sh_h0[4096];   // single-buffered, phase-separated
    __shared__ __align__(16) __half sh_h1[4096];
    __shared__ float sb0[512], sb1[512], swih0[1024];
    __shared__ float xin[12][NT_TILE], f3s[3][NT_TILE];

    for (int i = tid; i < 512; i += CTA_THREADS) { sb0[i] = g_b0c[i]; sb1[i] = g_b1c[i]; }
    for (int i = tid; i < 1024; i += CTA_THREADS) swih0[i] = W_ih0[i];
    for (int i = tid; i < 12 * NT_TILE; i += CTA_THREADS) {
        int f = i >> 5, n = i & 31;
        int gt = track0 + n, b = gt / NTRK, t = gt - b * NTRK;
        xin[f][n] = tf[((size_t)b * NFEAT + 6 + f) * NTRK + t];
    }
    for (int i = tid; i < 3 * NT_TILE; i += CTA_THREADS) {
        int f = i >> 5, n = i & 31;
        int gt = track0 + n, b = gt / NTRK, t = gt - b * NTRK;
        f3s[f][n] = tf[((size_t)b * NFEAT + f) * NTRK + t];
    }
    __syncthreads();

    float cst0A[8], cst0B[8], cst1A[8], cst1B[8];
#pragma unroll
    for (int i = 0; i < 8; ++i) { cst0A[i] = 0.f; cst0B[i] = 0.f; cst1A[i] = 0.f; cst1B[i] = 0.f; }

    float accA[4][2][4];   // in-flight accumulators, group A
    float accB[4][2][4];   // group B

    // layer-0 preact init: bias + W_ih0 * x_t  (x dim = 2), one 16-track group
    auto l0_init = [&](float (&acc)[4][2][4], int t, int g16) {
#pragma unroll
        for (int g = 0; g < 4; ++g)
#pragma unroll
            for (int uu = 0; uu < 2; ++uu) {
                int row = g * 128 + w16 + lr + 8 * uu;
                float bv = sb0[row];
                float w0v = swih0[row * 2 + 0];
                float w1v = swih0[row * 2 + 1];
#pragma unroll
                for (int nt = 0; nt < 2; ++nt)
#pragma unroll
                    for (int dd = 0; dd < 2; ++dd) {
                        int n = g16 + nt * 8 + c2 + dd;
                        acc[g][nt][uu * 2 + dd] =
                            fmaf(w1v, xin[2 * t + 1][n], fmaf(w0v, xin[2 * t + 0][n], bv));
                    }
            }
    };
    auto l1_init = [&](float (&acc)[4][2][4]) {
#pragma unroll
        for (int g = 0; g < 4; ++g)
#pragma unroll
            for (int uu = 0; uu < 2; ++uu) {
                float b = sb1[g * 128 + w16 + lr + 8 * uu];
#pragma unroll
                for (int nt = 0; nt < 2; ++nt) {
                    acc[g][nt][uu * 2 + 0] = b;
                    acc[g][nt][uu * 2 + 1] = b;
                }
            }
    };

#pragma unroll 1
    for (int t = 0; t < TSTEPS; ++t) {
        // ---- P1: issue G0A ; drain E1B(t-1) ----
        l0_init(accA, t, 0);
        if (t > 0) {
            gemm_frag<4, 8, 2>(accA, P_hh0 + w * 8192, sh_h0, lane, 0);
            epi_lstm(accB, cst1B, sh_h1, 16, w16, lr, c2);
        }
        __syncthreads();
        // ---- P2: issue G0B ; drain E0A ----
        l0_init(accB, t, 16);
        if (t > 0)
            gemm_frag<4, 8, 2>(accB, P_hh0 + w * 8192, sh_h0, lane, 16);
        epi_lstm(accA, cst0A, sh_h0, 0, w16, lr, c2);
        __syncthreads();
        // ---- P3: issue G1A ; drain E0B ----
        l1_init(accA);
        gemm_frag<4, 8, 2>(accA, P_ih1 + w * 8192, sh_h0, lane, 0);
        if (t > 0)
            gemm_frag<4, 8, 2>(accA, P_hh1 + w * 8192, sh_h1, lane, 0);
        epi_lstm(accB, cst0B, sh_h0, 16, w16, lr, c2);
        __syncthreads();
        // ---- P4: issue G1B ; drain E1A ----
        l1_init(accB);
        gemm_frag<4, 8, 2>(accB, P_ih1 + w * 8192, sh_h0, lane, 16);
        if (t > 0)
            gemm_frag<4, 8, 2>(accB, P_hh1 + w * 8192, sh_h1, lane, 16);
        epi_lstm(accA, cst1A, sh_h1, 0, w16, lr, c2);
        __syncthreads();
    }
    // final E1B(t=5)
    epi_lstm(accB, cst1B, sh_h1, 16, w16, lr, c2);
    __syncthreads();

    // ---------- MLP layer 0: relu(b0 + W0[:,0:3]*f3 + W0[:,3:131]*h1) ----------
    {
        float macc[2][4][4];
#pragma unroll
        for (int mt = 0; mt < 2; ++mt)
#pragma unroll
            for (int du = 0; du < 2; ++du) {
                int row = w * 32 + mt * 16 + lr + 8 * du;
                float bv = mb0[row];
                float w0v = mw0[row * 131 + 0];
                float w1v = mw0[row * 131 + 1];
                float w2v = mw0[row * 131 + 2];
#pragma unroll
                for (int nt = 0; nt < 4; ++nt)
#pragma unroll
                    for (int dd = 0; dd < 2; ++dd) {
                        int n = nt * 8 + c2 + dd;
                        float a = bv;
                        a = fmaf(w0v, f3s[0][n], a);
                        a = fmaf(w1v, f3s[1][n], a);
                        a = fmaf(w2v, f3s[2][n], a);
                        macc[mt][nt][du * 2 + dd] = a;
                    }
            }
        gemm_frag<2, 8, 4>(macc, P_w0 + w * 4096, sh_h1, lane, 0);
        __syncthreads();                       // all h1 reads complete

        // relu -> m2 fragments: units 0..127 into sh_h0, 128..255 into sh_h1
#pragma unroll
        for (int mt = 0; mt < 2; ++mt)
#pragma unroll
            for (int nt = 0; nt < 4; ++nt)
#pragma unroll
                for (int idx = 0; idx < 4; ++idx) {
                    float v = fmaxf(macc[mt][nt][idx], 0.f);
                    int u = w * 32 + mt * 16 + lr + 8 * (idx >> 1);
                    int n = nt * 8 + c2 + (idx & 1);
                    if (u < 128) sh_h0[hb_widx(u, n)] = __float2half_rn(v);
                    else         sh_h1[hb_widx(u - 128, n)] = __float2half_rn(v);
                }
    }
    __syncthreads();

    // ---------- MLP layer 1: out = b1 + W1 * m2 ----------
    {
        float oacc[2][4][4];
#pragma unroll
        for (int mt = 0; mt < 2; ++mt)
#pragma unroll
            for (int du = 0; du < 2; ++du) {
                float bv = mb1[w * 32 + mt * 16 + lr + 8 * du];
#pragma unroll
                for (int nt = 0; nt < 4; ++nt) {
                    oacc[mt][nt][du * 2 + 0] = bv;
                    oacc[mt][nt][du * 2 + 1] = bv;
                }
            }
        // K = 256: kh=0 (units 0..127) from sh_h0, kh=1 (units 128..255) from sh_h1
        gemm_frag<2, 8, 4>(oacc, P_w1 + w * 8192,        sh_h0, lane, 0);
        gemm_frag<2, 8, 4>(oacc, P_w1 + w * 8192 + 4096, sh_h1, lane, 0);

#pragma unroll
        for (int mt = 0; mt < 2; ++mt)
#pragma unroll
            for (int nt = 0; nt < 4; ++nt)
#pragma unroll
                for (int idx = 0; idx < 4; ++idx) {
                    int row = w * 32 + mt * 16 + lr + 8 * (idx >> 1);
                    int n = nt * 8 + c2 + (idx & 1);
                    out[(size_t)(track0 + n) * HID + row] = oacc[mt][nt][idx];
                }
    }
}

// ---------------- pos encoding ----------------
__global__ void pos_kernel(const float* __restrict__ tf, float* __restrict__ out)
{
    int idx = blockIdx.x * blockDim.x + threadIdx.x;
    if (idx >= NTRACK * 128) return;
    int gt = idx >> 7;
    int fi = idx & 127;
    int b = gt / NTRK, t = gt - b * NTRK;
    int coord = (fi < 64) ? 3 : 4;             // eta then phi
    float x = tf[((size_t)b * NFEAT + coord) * NTRK + t];
    int f = fi & 63;
    float p = x * g_posmul[f];
    float v = (f & 1) ? __cosf(p) : __sinf(p);
    out[(size_t)OUT_POS + (size_t)gt * 128 + fi] = v;
}

// ---------------- logpt / eta / phi passthrough ----------------
__global__ void scal_kernel(const float* __restrict__ tf, float* __restrict__ out)
{
    int gt = blockIdx.x * blockDim.x + threadIdx.x;
    if (gt >= NTRACK) return;
    int b = gt / NTRK, t = gt - b * NTRK;
    out[OUT_LOGPT + gt] = tf[((size_t)b * NFEAT + 2) * NTRK + t];
    out[OUT_ETA   + gt] = tf[((size_t)b * NFEAT + 3) * NTRK + t];
    out[OUT_PHI   + gt] = tf[((size_t)b * NFEAT + 4) * NTRK + t];
}

// ---------------- launch ----------------
extern "C" void kernel_launch(void* const* d_in, const int* in_sizes, int n_in,
                              void* d_out, int out_size)
{
    (void)in_sizes; (void)n_in; (void)out_size;
    const float* tf = (const float*)d_in[0];
    float* out = (float*)d_out;

    prep_kernel<<<128, 256>>>(
        (const float*)d_in[2],                       // W_hh0
        (const float*)d_in[3], (const float*)d_in[4],// b_ih0, b_hh0
        (const float*)d_in[5], (const float*)d_in[6],// W_ih1, W_hh1
        (const float*)d_in[7], (const float*)d_in[8],// b_ih1, b_hh1
        (const float*)d_in[9], (const float*)d_in[11]// mlp_w0, mlp_w1
    );

    lstm_mlp_kernel<<<NTRACK / NT_TILE, CTA_THREADS>>>(
        tf,
        (const float*)d_in[1],     // W_ih0
        (const float*)d_in[9],     // mlp_w0 (first 3 cols)
        (const float*)d_in[10],    // mlp_b0
        (const float*)d_in[12],    // mlp_b1
        out);

    pos_kernel<<<(NTRACK * 128 + 255) / 256, 256>>>(tf, out);
    scal_kernel<<<(NTRACK + 255) / 256, 256>>>(tf, out);
}

// round 11
// speedup vs baseline: 1.1517x; 1.1517x over previous
#include <cuda_runtime.h>
#include <cuda_fp16.h>
#include <math.h>

#define NFEAT 18
#define NTRK  1500
#define BSZ   64
#define NTRACK (BSZ*NTRK)        // 96000
#define HID   256
#define TSTEPS 6
#define NT_TILE 64               // tracks per CTA (2 groups x 32, one per warp-octet)
#define CTA_THREADS 512

// output layout offsets (floats)
#define OUT_POS   24576000       // 96000*256
#define OUT_LOGPT 36864000       // + 96000*128
#define OUT_ETA   36960000
#define OUT_PHI   37056000

#define SMEM_BYTES 77568

typedef unsigned long long u64;
typedef unsigned int u32;

// ---------------- device scratch: fragment-packed fp16 weights ----------------
// LSTM mats: ((((wi*4 + g)*8 + kc)*32 + lane)*4 + reg)*2 + dd
__device__ __align__(16) __half P_hh0[65536];
__device__ __align__(16) __half P_ih1[65536];
__device__ __align__(16) __half P_hh1[65536];
__device__ __align__(16) __half P_w0 [32768];   // [8wi][2mt][8kc][32][4][2]
__device__ __align__(16) __half P_w1 [65536];   // [8wi][2kh][2mt][8kc][32][4][2]
__device__ __align__(16) float g_b0c[512];      // b_ih0+b_hh0, row = g*128+unit
__device__ __align__(16) float g_b1c[512];
__device__ float g_posmul[64];

// ---------------- prep: pack weights into mma fragment order ----------------
__global__ void prep_kernel(const float* __restrict__ W_hh0,
                            const float* __restrict__ b_ih0, const float* __restrict__ b_hh0,
                            const float* __restrict__ W_ih1, const float* __restrict__ W_hh1,
                            const float* __restrict__ b_ih1, const float* __restrict__ b_hh1,
                            const float* __restrict__ mw0,   const float* __restrict__ mw1)
{
    int stride = gridDim.x * blockDim.x;
    int idx0 = blockIdx.x * blockDim.x + threadIdx.x;

    for (int i = idx0; i < 65536; i += stride) {
        int dd = i & 1, reg = (i >> 1) & 3, lane = (i >> 3) & 31;
        int kc = (i >> 8) & 7, g = (i >> 11) & 3, w = (i >> 13) & 7;
        int row = g * 128 + w * 16 + (lane >> 2) + 8 * (reg & 1);
        int col = kc * 16 + (lane & 3) * 2 + dd + 8 * (reg >> 1);
        P_hh0[i] = __float2half_rn(W_hh0[row * 128 + col]);
        P_ih1[i] = __float2half_rn(W_ih1[row * 128 + col]);
        P_hh1[i] = __float2half_rn(W_hh1[row * 128 + col]);
    }
    for (int i = idx0; i < 32768; i += stride) {
        int dd = i & 1, reg = (i >> 1) & 3, lane = (i >> 3) & 31;
        int kc = (i >> 8) & 7, mt = (i >> 11) & 1, w = (i >> 12) & 7;
        int row = w * 32 + mt * 16 + (lane >> 2) + 8 * (reg & 1);
        int k   = kc * 16 + (lane & 3) * 2 + dd + 8 * (reg >> 1);
        P_w0[i] = __float2half_rn(mw0[row * 131 + 3 + k]);
    }
    // MLP1, K=256, kh-major: [8w][2kh][2mt][8kc]
    for (int i = idx0; i < 65536; i += stride) {
        int dd = i & 1, reg = (i >> 1) & 3, lane = (i >> 3) & 31;
        int kc = (i >> 8) & 7, mt = (i >> 11) & 1, kh = (i >> 12) & 1, w = (i >> 13) & 7;
        int row = w * 32 + mt * 16 + (lane >> 2) + 8 * (reg & 1);
        int k   = (kh * 8 + kc) * 16 + (lane & 3) * 2 + dd + 8 * (reg >> 1);
        P_w1[i] = __float2half_rn(mw1[row * 256 + k]);
    }
    for (int i = idx0; i < 512; i += stride) {
        g_b0c[i] = b_ih0[i] + b_hh0[i];
        g_b1c[i] = b_ih1[i] + b_hh1[i];
    }
    for (int i = idx0; i < 64; i += stride) {
        float e = (float)(2 * (i >> 1)) * (1.0f / 64.0f);
        g_posmul[i] = 6.283185307179586f / powf(10000.0f, e);
    }
}

// ---------------- activations (MUFU.TANH based) ----------------
__device__ __forceinline__ float tanh_mufu(float x) {
    float r; asm("tanh.approx.f32 %0, %1;" : "=f"(r) : "f"(x)); return r;
}
__device__ __forceinline__ float sigf(float x) {
    return fmaf(tanh_mufu(0.5f * x), 0.5f, 0.5f);
}

// ---------------- mma.sync wrapper ----------------
__device__ __forceinline__ void mma16816(float c[4], u32 a0, u32 a1, u32 a2, u32 a3,
                                         u32 b0, u32 b1) {
    asm("mma.sync.aligned.m16n8k16.row.col.f32.f16.f16.f32 "
        "{%0,%1,%2,%3}, {%4,%5,%6,%7}, {%8,%9}, {%0,%1,%2,%3};"
        : "+f"(c[0]), "+f"(c[1]), "+f"(c[2]), "+f"(c[3])
        : "r"(a0), "r"(a1), "r"(a2), "r"(a3), "r"(b0), "r"(b1));
}

// hB layout for 64-track buffers:
//   half_idx = ((kc*4 + c)*64 + n)*4 + kp*2 + dd,  unit u = kc*16 + 2c + dd + 8kp
__device__ __forceinline__ int hb64(int u, int n) {
    return ((u >> 4) * 4 + ((u & 7) >> 1)) * 256 + n * 4 + ((u >> 3) & 1) * 2 + (u & 1);
}

// fragment GEMM over one 32-track group: acc[MT][4][4] += Wpacked * B(hB cols g32..g32+31)
template<int MT, int NKC>
__device__ __forceinline__ void gemm_frag(float acc[][4][4],
                                          const __half* __restrict__ pw,
                                          const __half* __restrict__ hB, int lane, int g32)
{
    const int c = lane & 3, colr = lane >> 2;
#pragma unroll
    for (int kc = 0; kc < NKC; ++kc) {
        u64 bv[4];
#pragma unroll
        for (int nt = 0; nt < 4; ++nt)
            bv[nt] = *reinterpret_cast<const u64*>(hB + ((kc * 4 + c) * 64 + g32 + nt * 8 + colr) * 4);
#pragma unroll
        for (int mt = 0; mt < MT; ++mt) {
            uint4 a = *reinterpret_cast<const uint4*>(pw + ((mt * NKC + kc) * 32 + lane) * 8);
#pragma unroll
            for (int nt = 0; nt < 4; ++nt)
                mma16816(acc[mt][nt], a.x, a.y, a.z, a.w,
                         (u32)bv[nt], (u32)(bv[nt] >> 32));
        }
    }
}

// ---------------- LSTM epilogue: one warp's 16 units x its 32-track group ----------------
__device__ __forceinline__ void epi_lstm(float acc[4][4][4], float* cst, __half* hbuf,
                                         int g32, int w16, int lr, int c2)
{
#pragma unroll
    for (int nt = 0; nt < 4; ++nt)
#pragma unroll
        for (int idx = 0; idx < 4; ++idx) {
            float iv = sigf(acc[0][nt][idx]);
            float fv = sigf(acc[1][nt][idx]);
            float gv = tanh_mufu(acc[2][nt][idx]);
            float ov = sigf(acc[3][nt][idx]);
            float& cc = cst[nt * 4 + idx];
            cc = fv * cc + iv * gv;
            float h = ov * tanh_mufu(cc);
            int u = w16 + lr + 8 * (idx >> 1);
            int n = g32 + nt * 8 + c2 + (idx & 1);
            hbuf[hb64(u, n)] = __float2half_rn(h);
        }
}

// ---------------- fused LSTM + MLP (tensor-core, warp-paired 64-track CTA) ----------------
__global__ void __launch_bounds__(CTA_THREADS, 1)
lstm_mlp_kernel(const float* __restrict__ tf,
                const float* __restrict__ W_ih0,   // [512][2] row-major
                const float* __restrict__ mw0,     // [256][131]
                const float* __restrict__ mb0,
                const float* __restrict__ mb1,
                float* __restrict__ out)
{
    extern __shared__ __align__(16) char smem[];
    __half* sh_h0 = (__half*)smem;                 // [2][8192] double-buffered
    __half* sh_h1 = (__half*)(smem + 32768);       // [2][8192]
    float* sb0   = (float*)(smem + 65536);         // [512]
    float* sb1   = sb0 + 512;                      // [512]
    float* swih0 = sb1 + 512;                      // [1024]
    float* xin   = swih0 + 1024;                   // [12][64]
    float* f3s   = xin + 768;                      // [3][64]

    const int tid  = threadIdx.x;
    const int lane = tid & 31;
    const int w    = tid >> 5;           // 0..15
    const int wi   = w & 7;              // unit-slice id (weight slice)
    const int g32  = (w >> 3) * 32;      // track-group offset
    const int track0 = blockIdx.x * NT_TILE;
    const int lr = lane >> 2, c2 = (lane & 3) * 2;
    const int w16 = wi * 16;

    for (int i = tid; i < 512; i += CTA_THREADS) { sb0[i] = g_b0c[i]; sb1[i] = g_b1c[i]; }
    for (int i = tid; i < 1024; i += CTA_THREADS) swih0[i] = W_ih0[i];
    for (int i = tid; i < 12 * 64; i += CTA_THREADS) {
        int f = i >> 6, n = i & 63;
        int gt = track0 + n, b = gt / NTRK, t = gt - b * NTRK;
        xin[f * 64 + n] = tf[((size_t)b * NFEAT + 6 + f) * NTRK + t];
    }
    for (int i = tid; i < 3 * 64; i += CTA_THREADS) {
        int f = i >> 6, n = i & 63;
        int gt = track0 + n, b = gt / NTRK, t = gt - b * NTRK;
        f3s[f * 64 + n] = tf[((size_t)b * NFEAT + f) * NTRK + t];
    }
    __syncthreads();

    float cst0[16], cst1[16];
#pragma unroll
    for (int i = 0; i < 16; ++i) { cst0[i] = 0.f; cst1[i] = 0.f; }

#pragma unroll 1
    for (int t = 0; t < TSTEPS; ++t) {
        const int cur = t & 1, prv = cur ^ 1;
        float acc[4][4][4];

        // ---------- layer 0: acc = bias + W_ih0 * x_t (+ W_hh0 * h0_prev) ----------
#pragma unroll
        for (int g = 0; g < 4; ++g)
#pragma unroll
            for (int uu = 0; uu < 2; ++uu) {
                int row = g * 128 + w16 + lr + 8 * uu;
                float bv = sb0[row];
                float w0v = swih0[row * 2 + 0];
                float w1v = swih0[row * 2 + 1];
#pragma unroll
                for (int nt = 0; nt < 4; ++nt)
#pragma unroll
                    for (int dd = 0; dd < 2; ++dd) {
                        int n = g32 + nt * 8 + c2 + dd;
                        acc[g][nt][uu * 2 + dd] =
                            fmaf(w1v, xin[(2 * t + 1) * 64 + n],
                                 fmaf(w0v, xin[(2 * t + 0) * 64 + n], bv));
                    }
            }
        if (t > 0)
            gemm_frag<4, 8>(acc, P_hh0 + wi * 8192, sh_h0 + prv * 8192, lane, g32);
        epi_lstm(acc, cst0, sh_h0 + cur * 8192, g32, w16, lr, c2);
        __syncthreads();

        // ---------- layer 1: acc = bias + W_ih1*h0[cur] (+ W_hh1*h1_prev) ----------
#pragma unroll
        for (int g = 0; g < 4; ++g)
#pragma unroll
            for (int uu = 0; uu < 2; ++uu) {
                float b = sb1[g * 128 + w16 + lr + 8 * uu];
#pragma unroll
                for (int nt = 0; nt < 4; ++nt) {
                    acc[g][nt][uu * 2 + 0] = b;
                    acc[g][nt][uu * 2 + 1] = b;
                }
            }
        gemm_frag<4, 8>(acc, P_ih1 + wi * 8192, sh_h0 + cur * 8192, lane, g32);
        if (t > 0)
            gemm_frag<4, 8>(acc, P_hh1 + wi * 8192, sh_h1 + prv * 8192, lane, g32);
        epi_lstm(acc, cst1, sh_h1 + cur * 8192, g32, w16, lr, c2);
        __syncthreads();
    }

    const __half* hB1f = sh_h1 + ((TSTEPS - 1) & 1) * 8192;   // final h1 (buf 1)

    // ---------- MLP layer 0: relu(b0 + W0[:,0:3]*f3 + W0[:,3:131]*h1) ----------
    {
        float macc[2][4][4];
#pragma unroll
        for (int mt = 0; mt < 2; ++mt)
#pragma unroll
            for (int du = 0; du < 2; ++du) {
                int row = wi * 32 + mt * 16 + lr + 8 * du;
                float bv = mb0[row];
                float w0v = mw0[row * 131 + 0];
                float w1v = mw0[row * 131 + 1];
                float w2v = mw0[row * 131 + 2];
#pragma unroll
                for (int nt = 0; nt < 4; ++nt)
#pragma unroll
                    for (int dd = 0; dd < 2; ++dd) {
                        int n = g32 + nt * 8 + c2 + dd;
                        float a = bv;
                        a = fmaf(w0v, f3s[0 * 64 + n], a);
                        a = fmaf(w1v, f3s[1 * 64 + n], a);
                        a = fmaf(w2v, f3s[2 * 64 + n], a);
                        macc[mt][nt][du * 2 + dd] = a;
                    }
            }
        gemm_frag<2, 8>(macc, P_w0 + wi * 4096, hB1f, lane, g32);

        // relu -> m2: units 0..127 into sh_h0 buf0, units 128..255 into sh_h0 buf1
        // (sh_h1 buf1 = h1 still being read by other warps; untouched here)
#pragma unroll
        for (int mt = 0; mt < 2; ++mt)
#pragma unroll
            for (int nt = 0; nt < 4; ++nt)
#pragma unroll
                for (int idx = 0; idx < 4; ++idx) {
                    float v = fmaxf(macc[mt][nt][idx], 0.f);
                    int u = wi * 32 + mt * 16 + lr + 8 * (idx >> 1);
                    int n = g32 + nt * 8 + c2 + (idx & 1);
                    if (u < 128) sh_h0[hb64(u, n)] = __float2half_rn(v);
                    else         sh_h0[8192 + hb64(u - 128, n)] = __float2half_rn(v);
                }
    }
    __syncthreads();

    // ---------- MLP layer 1: out = b1 + W1 * m2 ----------
    {
        float oacc[2][4][4];
#pragma unroll
        for (int mt = 0; mt < 2; ++mt)
#pragma unroll
            for (int du = 0; du < 2; ++du) {
                float bv = mb1[wi * 32 + mt * 16 + lr + 8 * du];
#pragma unroll
                for (int nt = 0; nt < 4; ++nt) {
                    oacc[mt][nt][du * 2 + 0] = bv;
                    oacc[mt][nt][du * 2 + 1] = bv;
                }
            }
        // K = 256: kh=0 (units 0..127) from sh_h0 buf0, kh=1 from sh_h0 buf1
        gemm_frag<2, 8>(oacc, P_w1 + wi * 8192,        sh_h0,        lane, g32);
        gemm_frag<2, 8>(oacc, P_w1 + wi * 8192 + 4096, sh_h0 + 8192, lane, g32);

#pragma unroll
        for (int mt = 0; mt < 2; ++mt)
#pragma unroll
            for (int nt = 0; nt < 4; ++nt)
#pragma unroll
                for (int idx = 0; idx < 4; ++idx) {
                    int row = wi * 32 + mt * 16 + lr + 8 * (idx >> 1);
                    int n = g32 + nt * 8 + c2 + (idx & 1);
                    out[(size_t)(track0 + n) * HID + row] = oacc[mt][nt][idx];
                }
    }
}

// ---------------- pos encoding ----------------
__global__ void pos_kernel(const float* __restrict__ tf, float* __restrict__ out)
{
    int idx = blockIdx.x * blockDim.x + threadIdx.x;
    if (idx >= NTRACK * 128) return;
    int gt = idx >> 7;
    int fi = idx & 127;
    int b = gt / NTRK, t = gt - b * NTRK;
    int coord = (fi < 64) ? 3 : 4;             // eta then phi
    float x = tf[((size_t)b * NFEAT + coord) * NTRK + t];
    int f = fi & 63;
    float p = x * g_posmul[f];
    float v = (f & 1) ? __cosf(p) : __sinf(p);
    out[(size_t)OUT_POS + (size_t)gt * 128 + fi] = v;
}

// ---------------- logpt / eta / phi passthrough ----------------
__global__ void scal_kernel(const float* __restrict__ tf, float* __restrict__ out)
{
    int gt = blockIdx.x * blockDim.x + threadIdx.x;
    if (gt >= NTRACK) return;
    int b = gt / NTRK, t = gt - b * NTRK;
    out[OUT_LOGPT + gt] = tf[((size_t)b * NFEAT + 2) * NTRK + t];
    out[OUT_ETA   + gt] = tf[((size_t)b * NFEAT + 3) * NTRK + t];
    out[OUT_PHI   + gt] = tf[((size_t)b * NFEAT + 4) * NTRK + t];
}

// ---------------- launch ----------------
extern "C" void kernel_launch(void* const* d_in, const int* in_sizes, int n_in,
                              void* d_out, int out_size)
{
    (void)in_sizes; (void)n_in; (void)out_size;
    const float* tf = (const float*)d_in[0];
    float* out = (float*)d_out;

    cudaFuncSetAttribute(lstm_mlp_kernel,
                         cudaFuncAttributeMaxDynamicSharedMemorySize, SMEM_BYTES);

    prep_kernel<<<128, 256>>>(
        (const float*)d_in[2],                       // W_hh0
        (const float*)d_in[3], (const float*)d_in[4],// b_ih0, b_hh0
        (const float*)d_in[5], (const float*)d_in[6],// W_ih1, W_hh1
        (const float*)d_in[7], (const float*)d_in[8],// b_ih1, b_hh1
        (const float*)d_in[9], (const float*)d_in[11]// mlp_w0, mlp_w1
    );

    lstm_mlp_kernel<<<NTRACK / NT_TILE, CTA_THREADS, SMEM_BYTES>>>(
        tf,
        (const float*)d_in[1],     // W_ih0
        (const float*)d_in[9],     // mlp_w0 (first 3 cols)
        (const float*)d_in[10],    // mlp_b0
        (const float*)d_in[12],    // mlp_b1
        out);

    pos_kernel<<<(NTRACK * 128 + 255) / 256, 256>>>(tf, out);
    scal_kernel<<<(NTRACK + 255) / 256, 256>>>(tf, out);
}